// round 6
// baseline (speedup 1.0000x reference)
#include <cuda_runtime.h>
#include <cstdint>

#define NB 8192      // batch
#define NA 128       // attr dim
#define NH 256       // hidden
#define NV 64        // vocab
#define NL 20        // rollout length
#define NBR 56       // batch rows per block
#define NBLK 147     // ceil(NB/NBR)
#define NT 512       // threads per block
#define HP 58        // padded b-stride for h smem (even for f32x2)
#define WTS 512      // W tile row stride (floats)
#define BUFF 8192    // floats per W tile buffer

// ---- shared memory layout (float offsets) ----
#define OFF_HA   0
#define OFF_HB   (NH*HP)               // 14848
#define OFF_WT   (2*NH*HP)             // 29696: 3 tile buffers
#define OFF_LG   (OFF_WT + 3*BUFF)     // 54272: logits 56 x 64
#define OFF_CH   (OFF_LG + NBR*64)     // 57856 (int[56])
#define OFF_SLP  (OFF_CH + 56)
#define OFF_PLP  (OFF_SLP + 56)
#define OFF_EP   (OFF_PLP + 56)
#define SMEM_FLOATS (OFF_EP + 56)      // 58080 floats = 232,320 B

// ---- reordered weight scratch ----
__device__ __align__(16) float  g_WhhR[2*256*512];   // [pass][k 256][n' = g*128+nl]
__device__ __align__(16) float4 g_WihR4[64*256];     // [ch][hh] -> 4 gates
__device__ __align__(16) float  g_WaR[128*256];      // [k][hh]
__device__ __align__(16) float4 g_biasR4[256];       // [hh] -> 4 gates (b_ih+b_hh)
__device__ __align__(16) float  g_WvT[256*64];       // [k][v] transposed W_v

struct Keys { unsigned int a[NL]; unsigned int b[NL]; };

typedef unsigned long long ull;

// ---------------- packed f32x2 helpers ----------------
__device__ __forceinline__ void ffma2(ull &d, ull a, ull b) {
    asm("fma.rn.f32x2 %0, %1, %2, %3;" : "=l"(d) : "l"(a), "l"(b), "l"(d));
}
__device__ __forceinline__ ull pack2(float lo, float hi) {
    ull r; asm("mov.b64 %0, {%1, %2};" : "=l"(r) : "f"(lo), "f"(hi)); return r;
}
__device__ __forceinline__ void unpack2(ull v, float &lo, float &hi) {
    asm("mov.b64 {%0, %1}, %2;" : "=f"(lo), "=f"(hi) : "l"(v));
}

// ---------------- cp.async helpers ----------------
__device__ __forceinline__ void cp16(float* dst_smem, const float* src) {
    unsigned sdst = (unsigned)__cvta_generic_to_shared(dst_smem);
    asm volatile("cp.async.cg.shared.global [%0], [%1], 16;" :: "r"(sdst), "l"(src));
}
__device__ __forceinline__ void cp_commit() { asm volatile("cp.async.commit_group;"); }
__device__ __forceinline__ void cp_wait1() { asm volatile("cp.async.wait_group 1;"); }
__device__ __forceinline__ void cp_wait0() { asm volatile("cp.async.wait_group 0;"); }

// ---------------- Threefry-2x32 (20 rounds), matches JAX ----------------
__host__ __device__ __forceinline__ uint32_t rotl32(uint32_t x, int r) {
    return (x << r) | (x >> (32 - r));
}
__host__ __device__ __forceinline__ void threefry2x32(
    uint32_t k0, uint32_t k1, uint32_t x0, uint32_t x1,
    uint32_t& o0, uint32_t& o1)
{
    uint32_t ks0 = k0, ks1 = k1, ks2 = k0 ^ k1 ^ 0x1BD11BDAu;
    x0 += ks0; x1 += ks1;
#define TF_RND(r) { x0 += x1; x1 = rotl32(x1, (r)); x1 ^= x0; }
    TF_RND(13) TF_RND(15) TF_RND(26) TF_RND(6)
    x0 += ks1; x1 += ks2 + 1u;
    TF_RND(17) TF_RND(29) TF_RND(16) TF_RND(24)
    x0 += ks2; x1 += ks0 + 2u;
    TF_RND(13) TF_RND(15) TF_RND(26) TF_RND(6)
    x0 += ks0; x1 += ks1 + 3u;
    TF_RND(17) TF_RND(29) TF_RND(16) TF_RND(24)
    x0 += ks1; x1 += ks2 + 4u;
    TF_RND(13) TF_RND(15) TF_RND(26) TF_RND(6)
    x0 += ks2; x1 += ks0 + 5u;
#undef TF_RND
    o0 = x0; o1 = x1;
}

__device__ __forceinline__ float sigf(float x) { return 1.0f / (1.0f + expf(-x)); }

// gumbel from raw bits — identical formula to rounds 1-4
__device__ __forceinline__ float gumbel_from(uint32_t sk0, uint32_t sk1, uint32_t ctr) {
    uint32_t o0, o1;
    threefry2x32(sk0, sk1, 0u, ctr, o0, o1);
    uint32_t bits = o0 ^ o1;
    float f = __uint_as_float((bits >> 9) | 0x3f800000u) - 1.0f;
    const float TINY = 1.17549435e-38f;
    float u = fmaxf(TINY, f * (1.0f - TINY) + TINY);
    return -logf(-logf(u));
}

// ---------------- prep: reorder weights ----------------
__global__ void prep_kernel(const float* __restrict__ Whh, const float* __restrict__ Wih,
                            const float* __restrict__ Wa,  const float* __restrict__ bih,
                            const float* __restrict__ bhh, const float* __restrict__ Wv)
{
    int idx = blockIdx.x * blockDim.x + threadIdx.x;
    if (idx < 2*256*512) {
        int p = idx >> 17, rem = idx & 131071, k = rem >> 9, n = rem & 511;
        int g = n >> 7, nl = n & 127;
        g_WhhR[idx] = Whh[(size_t)(g*256 + p*128 + nl) * 256 + k];
    }
    if (idx < 64*256*4) {
        int ch = idx >> 10, hh = (idx >> 2) & 255, g = idx & 3;
        ((float*)g_WihR4)[idx] = Wih[(size_t)(g*256 + hh) * 64 + ch];
    }
    if (idx < 128*256) {
        int k = idx >> 8, hh = idx & 255;
        g_WaR[idx] = Wa[(size_t)hh * 128 + k];
    }
    if (idx < 256*64) {
        int k = idx >> 6, v = idx & 63;
        g_WvT[idx] = Wv[(size_t)v * NH + k];
    }
    if (idx < 1024) {
        int hh = idx >> 2, g = idx & 3;
        int gn = g*256 + hh;
        ((float*)g_biasR4)[idx] = bih[gn] + bhh[gn];
    }
}

// ---------------- W tile async load: 16 k rows x 512 cols ----------------
__device__ __forceinline__ void issue_tile(float* buf, int kt, int tid) {
    const float* src = g_WhhR + (size_t)kt * 16 * 512;
#pragma unroll
    for (int s = 0; s < 4; s++) {
        int i = tid + s * NT;
        int kk = i >> 7, c4 = i & 127;
        cp16(buf + kk * WTS + c4 * 4, src + kk * 512 + c4 * 4);
    }
    cp_commit();
}

// ---------------- LSTM epilogue for one pass (bit-identical to R3/R4) ----------------
template<bool hasX>
__device__ __forceinline__ void lstm_epilogue(float* sm, float* hnew, float* cc,
                                              ull (&acc)[7][4], int p, int nl, int b0)
{
    const int hh = p * 128 + nl;
    float4 bb = g_biasR4[hh];
    const int* s_ch = (const int*)sm + OFF_CH;
#pragma unroll
    for (int i = 0; i < 7; i++) {
        float a0[4], a1[4];
#pragma unroll
        for (int g = 0; g < 4; g++) unpack2(acc[i][g], a0[g], a1[g]);
        float hn[2];
#pragma unroll
        for (int ro = 0; ro < 2; ro++) {
            float* ar = ro ? a1 : a0;
            int b = b0 + 2 * i + ro;
            float xx = 0.f, xy = 0.f, xz = 0.f, xw = 0.f;
            if (hasX) {
                int ch = s_ch[b];
                float4 xg = g_WihR4[ch * 256 + hh];
                xx = xg.x; xy = xg.y; xz = xg.z; xw = xg.w;
            }
            float gi = ar[0] + bb.x + xx;
            float gf = ar[1] + bb.y + xy;
            float gg = ar[2] + bb.z + xz;
            float go = ar[3] + bb.w + xw;
            float cv = cc[p * 14 + 2 * i + ro];
            float cn = sigf(gf) * cv + sigf(gi) * tanhf(gg);
            cc[p * 14 + 2 * i + ro] = cn;
            hn[ro] = sigf(go) * tanhf(cn);
        }
        *(ull*)(hnew + hh * HP + b0 + 2 * i) = pack2(hn[0], hn[1]);
    }
}

// ---------------- per-row reduction + gumbel sample (bit-identical to R4) ----------------
__device__ __forceinline__ void reduce_row(float* sm, int r, int base, int lane,
        float* __restrict__ out, int t, uint32_t sk0, uint32_t sk1)
{
    int* si = (int*)sm;
    int gb = base + r;
    float la0 = sm[OFF_LG + r * 64 + 2 * lane];
    float la1 = sm[OFF_LG + r * 64 + 2 * lane + 1];
    float m = fmaxf(la0, la1);
#pragma unroll
    for (int o = 16; o; o >>= 1) m = fmaxf(m, __shfl_xor_sync(0xffffffffu, m, o));
    float S = expf(la0 - m) + expf(la1 - m);
#pragma unroll
    for (int o = 16; o; o >>= 1) S += __shfl_xor_sync(0xffffffffu, S, o);
    float lse = logf(S);
    float lp0 = (la0 - m) - lse;
    float lp1 = (la1 - m) - lse;
    float pt = expf(lp0) * lp0 + expf(lp1) * lp1;
#pragma unroll
    for (int o = 16; o; o >>= 1) pt += __shfl_xor_sync(0xffffffffu, pt, o);
    float g0 = gumbel_from(sk0, sk1, (uint32_t)(gb * NV + 2 * lane));
    float g1 = gumbel_from(sk0, sk1, (uint32_t)(gb * NV + 2 * lane + 1));
    float z0 = la0 + g0, z1 = la1 + g1;
    float z; int idx;
    if (z1 > z0) { z = z1; idx = 2 * lane + 1; }
    else         { z = z0; idx = 2 * lane; }
#pragma unroll
    for (int o = 16; o; o >>= 1) {
        float oz = __shfl_xor_sync(0xffffffffu, z, o);
        int   oi = __shfl_xor_sync(0xffffffffu, idx, o);
        if (oz > z || (oz == z && oi < idx)) { z = oz; idx = oi; }
    }
    float lpA = __shfl_sync(0xffffffffu, lp0, idx >> 1);
    float lpB = __shfl_sync(0xffffffffu, lp1, idx >> 1);
    float lp = (idx & 1) ? lpB : lpA;
    if (lane == 0) {
        si[OFF_CH + r] = idx;
        sm[OFF_SLP + r] += lp;
        sm[OFF_PLP + r] += pt;
        sm[OFF_EP + r] *= expf(lp);
        if (gb < NB) out[(size_t)gb * NL + t] = (float)idx;
    }
}

// ---------------- one LSTM step with interleaved sampling of the PREVIOUS h ----------------
// GEMM for step t+1 runs over 32 k-tiles; sampling of h_t (=hcur) is spread over
// tiles 0..7 (logits chunks, partials in smem) and 8..11 (per-warp row reductions).
// ch_t is consumed by the pass-0 epilogue at tile 15.
template<bool hasX, bool doSample>
__device__ __forceinline__ void lstm_step(float* sm, const float* hcur, float* hnew,
                                          float* cc, int tid, int nl, int b0,
                                          const float* __restrict__ bv,
                                          float* __restrict__ out, int t, int base,
                                          uint32_t sk0, uint32_t sk1)
{
    float* bA = sm + OFF_WT;
    float* bB = bA + BUFF;
    float* bC = bB + BUFF;

    // sampling thread mapping (independent of GEMM mapping)
    const int sbg = tid >> 6;          // 8 groups of 7 rows
    const int v = tid & 63;
    const int b0s = sbg * 7;
    const int p0 = (sbg & 1) ? 1 : 0;  // aligned pair base
    const int sc = (sbg & 1) ? 0 : 6;  // leftover scalar row
    const int warp = tid >> 5, lane = tid & 31;

    issue_tile(bA, 0, tid);
    issue_tile(bB, 1, tid);

    ull acc[7][4];
#pragma unroll
    for (int i = 0; i < 7; i++)
#pragma unroll
        for (int g = 0; g < 4; g++) acc[i][g] = 0ull;

#pragma unroll 1
    for (int kt = 0; kt < 32; kt++) {
        if (kt < 31) cp_wait1(); else cp_wait0();
        __syncthreads();
        if (kt + 2 < 32) issue_tile(bC, kt + 2, tid);

        const float* wk = bA + nl;
        const float* hk = hcur + (kt & 15) * 16 * HP + b0;
#pragma unroll
        for (int kk = 0; kk < 16; kk++) {
            float w0 = wk[kk*WTS      ];
            float w1 = wk[kk*WTS + 128];
            float w2 = wk[kk*WTS + 256];
            float w3 = wk[kk*WTS + 384];
            ull W0 = pack2(w0, w0), W1 = pack2(w1, w1);
            ull W2 = pack2(w2, w2), W3 = pack2(w3, w3);
#pragma unroll
            for (int i = 0; i < 7; i++) {
                ull h2 = *(const ull*)(hk + kk * HP + 2 * i);
                ffma2(acc[i][0], h2, W0);
                ffma2(acc[i][1], h2, W1);
                ffma2(acc[i][2], h2, W2);
                ffma2(acc[i][3], h2, W3);
            }
        }

        if (doSample) {
            if (kt < 8) {
                // logits chunk: kk = kt*32 .. kt*32+31, partial sums live in LG smem
                ull accp[3]; float accs;
                if (kt == 0) {
                    float bvv = bv[v];
                    accp[0] = pack2(bvv, bvv);
                    accp[1] = accp[0];
                    accp[2] = accp[0];
                    accs = bvv;
                } else {
#pragma unroll
                    for (int j = 0; j < 3; j++) {
                        float lo = sm[OFF_LG + (b0s + p0 + 2*j    ) * 64 + v];
                        float hi = sm[OFF_LG + (b0s + p0 + 2*j + 1) * 64 + v];
                        accp[j] = pack2(lo, hi);
                    }
                    accs = sm[OFF_LG + (b0s + sc) * 64 + v];
                }
                const float* hs = hcur + b0s;
                const float* wvk = g_WvT + kt * 32 * 64 + v;
#pragma unroll 4
                for (int k2 = 0; k2 < 32; k2++) {
                    int kk = kt * 32 + k2;
                    float w = wvk[k2 * 64];
                    ull w2 = pack2(w, w);
                    ffma2(accp[0], *(const ull*)(hs + kk * HP + p0), w2);
                    ffma2(accp[1], *(const ull*)(hs + kk * HP + p0 + 2), w2);
                    ffma2(accp[2], *(const ull*)(hs + kk * HP + p0 + 4), w2);
                    accs = fmaf(hs[kk * HP + sc], w, accs);
                }
#pragma unroll
                for (int j = 0; j < 3; j++) {
                    float lo, hi; unpack2(accp[j], lo, hi);
                    sm[OFF_LG + (b0s + p0 + 2*j    ) * 64 + v] = lo;
                    sm[OFF_LG + (b0s + p0 + 2*j + 1) * 64 + v] = hi;
                }
                sm[OFF_LG + (b0s + sc) * 64 + v] = accs;
            } else if (kt < 12) {
                int r = warp + 16 * (kt - 8);
                if (r < NBR) reduce_row(sm, r, base, lane, out, t, sk0, sk1);
            }
        }

        if (kt == 15) {
            lstm_epilogue<hasX>(sm, hnew, cc, acc, 0, nl, b0);
#pragma unroll
            for (int i = 0; i < 7; i++)
#pragma unroll
                for (int g = 0; g < 4; g++) acc[i][g] = 0ull;
        }

        float* tmp = bA; bA = bB; bB = bC; bC = tmp;
    }
    lstm_epilogue<hasX>(sm, hnew, cc, acc, 1, nl, b0);
    __syncthreads();
}

// ---------------- standalone final sample (t = NL-1) ----------------
__device__ __forceinline__ void sample_final(float* sm, const float* hcur,
        const float* __restrict__ bv, float* __restrict__ out, int t, int base,
        int tid, uint32_t sk0, uint32_t sk1)
{
    const int sbg = tid >> 6;
    const int v = tid & 63;
    const int b0s = sbg * 7;
    const int p0 = (sbg & 1) ? 1 : 0;
    const int sc = (sbg & 1) ? 0 : 6;
    float bvv = bv[v];
    ull accp[3];
    accp[0] = pack2(bvv, bvv); accp[1] = accp[0]; accp[2] = accp[0];
    float accs = bvv;
    const float* hs = hcur + b0s;
    const float* wvk = g_WvT + v;
#pragma unroll 4
    for (int kk = 0; kk < NH; kk++) {
        float w = wvk[kk * 64];
        ull w2 = pack2(w, w);
        ffma2(accp[0], *(const ull*)(hs + kk * HP + p0), w2);
        ffma2(accp[1], *(const ull*)(hs + kk * HP + p0 + 2), w2);
        ffma2(accp[2], *(const ull*)(hs + kk * HP + p0 + 4), w2);
        accs = fmaf(hs[kk * HP + sc], w, accs);
    }
#pragma unroll
    for (int j = 0; j < 3; j++) {
        float lo, hi; unpack2(accp[j], lo, hi);
        sm[OFF_LG + (b0s + p0 + 2*j    ) * 64 + v] = lo;
        sm[OFF_LG + (b0s + p0 + 2*j + 1) * 64 + v] = hi;
    }
    sm[OFF_LG + (b0s + sc) * 64 + v] = accs;
    __syncthreads();

    const int warp = tid >> 5, lane = tid & 31;
    for (int r = warp; r < NBR; r += 16)
        reduce_row(sm, r, base, lane, out, t, sk0, sk1);
    __syncthreads();
}

// ---------------- fused persistent rollout kernel ----------------
__global__ __launch_bounds__(NT, 1) void sender_kernel(
    const float* __restrict__ attr, const float* __restrict__ bv,
    const float* __restrict__ ba, float* __restrict__ out, Keys keys)
{
    extern __shared__ float sm[];
    const int tid = threadIdx.x;
    const int bq = tid >> 7;        // 4 groups
    const int nl = tid & 127;       // 128 n-columns
    const int b0 = bq * 14;         // 14 rows (7 f32x2 pairs)
    const int base = blockIdx.x * NBR;

    float cc[28];
#pragma unroll
    for (int i = 0; i < 28; i++) cc[i] = 0.0f;

    if (tid < NBR) { sm[OFF_SLP + tid] = 0.0f; sm[OFF_PLP + tid] = 0.0f; sm[OFF_EP + tid] = 1.0f; }

    // stage attr tile [k 128][b] stride HP into tile-buffer area
    for (int idx = tid; idx < NBR * 32; idx += NT) {
        int b = idx >> 5, f4 = idx & 31;
        int gb = base + b;
        float4 a = make_float4(0.f, 0.f, 0.f, 0.f);
        if (gb < NB) a = ((const float4*)attr)[(size_t)gb * 32 + f4];
        sm[OFF_WT + (f4*4+0)*HP + b] = a.x;
        sm[OFF_WT + (f4*4+1)*HP + b] = a.y;
        sm[OFF_WT + (f4*4+2)*HP + b] = a.z;
        sm[OFF_WT + (f4*4+3)*HP + b] = a.w;
    }
    __syncthreads();

    // h0 = attr @ W_a^T + b_a  (identical arithmetic to R2-R4)
#pragma unroll
    for (int p = 0; p < 2; p++) {
        const int hh = p * 128 + nl;
        ull acc[7];
#pragma unroll
        for (int i = 0; i < 7; i++) acc[i] = 0ull;
        const float* wr = g_WaR + hh;
        const float* ak = sm + OFF_WT + b0;
#pragma unroll 4
        for (int k = 0; k < NA; k++) {
            float w = wr[k * 256];
            ull w2 = pack2(w, w);
#pragma unroll
            for (int i = 0; i < 7; i++) {
                ull h2 = *(const ull*)(ak + k * HP + 2 * i);
                ffma2(acc[i], h2, w2);
            }
        }
        float bbv = ba[hh];
#pragma unroll
        for (int i = 0; i < 7; i++) {
            float lo, hi; unpack2(acc[i], lo, hi);
            *(ull*)(sm + OFF_HA + hh * HP + b0 + 2 * i) = pack2(lo + bbv, hi + bbv);
        }
    }
    __syncthreads();

    float* hA = sm + OFF_HA;
    float* hB = sm + OFF_HB;

    // start-token step (x = 0): hA -> hB, no sampling yet
    lstm_step<false, false>(sm, hA, hB, cc, tid, nl, b0, bv, out, 0, base, 0u, 0u);

    float* hc = hB;
    float* hn = hA;
    // steps t = 0..18: sample(t) from hc interleaved with the gates GEMM hc -> hn
    for (int t = 0; t < NL - 1; t++) {
        lstm_step<true, true>(sm, hc, hn, cc, tid, nl, b0, bv, out, t, base,
                              keys.a[t], keys.b[t]);
        float* tmp = hc; hc = hn; hn = tmp;
    }
    // final sample t = 19 (no following LSTM step)
    sample_final(sm, hc, bv, out, NL - 1, base, tid, keys.a[NL-1], keys.b[NL-1]);

    for (int i = tid; i < NBR; i += NT) {
        int gb = base + i;
        if (gb < NB) {
            out[NB*NL + gb]        = sm[OFF_SLP + i];
            out[NB*NL + NB + gb]   = sm[OFF_PLP + i];
            out[NB*NL + 2*NB + gb] = sm[OFF_EP + i];
        }
    }
}

// ---------------- launcher ----------------
extern "C" void kernel_launch(void* const* d_in, const int* in_sizes, int n_in,
                              void* d_out, int out_size)
{
    const float* attr = (const float*)d_in[0];
    const float* W_a  = (const float*)d_in[1];
    const float* b_a  = (const float*)d_in[2];
    const float* W_ih = (const float*)d_in[3];
    const float* W_hh = (const float*)d_in[4];
    const float* b_ih = (const float*)d_in[5];
    const float* b_hh = (const float*)d_in[6];
    const float* W_v  = (const float*)d_in[7];
    const float* b_v  = (const float*)d_in[8];
    float* out = (float*)d_out;

    Keys keys;
    for (int t = 0; t < NL; t++) {
        uint32_t s0, s1;
        threefry2x32(0u, 42u, 0u, (uint32_t)t, s0, s1);
        keys.a[t] = s0; keys.b[t] = s1;
    }

    static int smem_set = 0;
    if (!smem_set) {
        cudaFuncSetAttribute(sender_kernel, cudaFuncAttributeMaxDynamicSharedMemorySize,
                             SMEM_FLOATS * sizeof(float));
        smem_set = 1;
    }

    prep_kernel<<<1024, 256>>>(W_hh, W_ih, W_a, b_ih, b_hh, W_v);
    sender_kernel<<<NBLK, NT, SMEM_FLOATS * sizeof(float)>>>(attr, b_v, b_a, out, keys);
}

// round 7
// speedup vs baseline: 1.2525x; 1.2525x over previous
#include <cuda_runtime.h>
#include <cstdint>

#define NB 8192      // batch
#define NA 128       // attr dim
#define NH 256       // hidden
#define NV 64        // vocab
#define NL 20        // rollout length
#define NBR 56       // batch rows per block
#define NBLK 147     // ceil(NB/NBR)
#define NT 512       // threads per block
#define HP 58        // padded b-stride for h smem (even; 58%8==2 avoids STS.64 bank pileup)

// ---- shared memory layout (float offsets) ----
#define OFF_HA   0
#define OFF_HB   (NH*HP)               // 14848
#define OFF_LG   (2*NH*HP)             // 29696: logits 56 x 64
#define OFF_CH   (OFF_LG + NBR*64)     // 33280 (int[56])
#define OFF_SLP  (OFF_CH + 56)
#define OFF_PLP  (OFF_SLP + 56)
#define OFF_EP   (OFF_PLP + 56)
#define SMEM_FLOATS (OFF_EP + 56)      // 33504 floats = 134,016 B

// ---- reordered weight scratch ----
// W_hh: [p 2][k 256][nl 128][g 4] float; +2048 pad for prefetch overrun
__device__ __align__(16) float  g_WhhR2[2*256*512 + 2048];
__device__ __align__(16) float4 g_WihR4[64*256];     // [ch][hh] -> 4 gates
__device__ __align__(16) float  g_WaR[128*256];      // [k][hh]
__device__ __align__(16) float4 g_biasR4[256];       // [hh] -> 4 gates (b_ih+b_hh)
__device__ __align__(16) float  g_WvT[256*64];       // [k][v] transposed W_v

struct Keys { unsigned int a[NL]; unsigned int b[NL]; };

typedef unsigned long long ull;

// ---------------- packed f32x2 helpers ----------------
__device__ __forceinline__ void ffma2(ull &d, ull a, ull b) {
    asm("fma.rn.f32x2 %0, %1, %2, %3;" : "=l"(d) : "l"(a), "l"(b), "l"(d));
}
__device__ __forceinline__ ull pack2(float lo, float hi) {
    ull r; asm("mov.b64 %0, {%1, %2};" : "=l"(r) : "f"(lo), "f"(hi)); return r;
}
__device__ __forceinline__ void unpack2(ull v, float &lo, float &hi) {
    asm("mov.b64 {%0, %1}, %2;" : "=f"(lo), "=f"(hi) : "l"(v));
}

// ---------------- Threefry-2x32 (20 rounds), matches JAX ----------------
__host__ __device__ __forceinline__ uint32_t rotl32(uint32_t x, int r) {
    return (x << r) | (x >> (32 - r));
}
__host__ __device__ __forceinline__ void threefry2x32(
    uint32_t k0, uint32_t k1, uint32_t x0, uint32_t x1,
    uint32_t& o0, uint32_t& o1)
{
    uint32_t ks0 = k0, ks1 = k1, ks2 = k0 ^ k1 ^ 0x1BD11BDAu;
    x0 += ks0; x1 += ks1;
#define TF_RND(r) { x0 += x1; x1 = rotl32(x1, (r)); x1 ^= x0; }
    TF_RND(13) TF_RND(15) TF_RND(26) TF_RND(6)
    x0 += ks1; x1 += ks2 + 1u;
    TF_RND(17) TF_RND(29) TF_RND(16) TF_RND(24)
    x0 += ks2; x1 += ks0 + 2u;
    TF_RND(13) TF_RND(15) TF_RND(26) TF_RND(6)
    x0 += ks0; x1 += ks1 + 3u;
    TF_RND(17) TF_RND(29) TF_RND(16) TF_RND(24)
    x0 += ks1; x1 += ks2 + 4u;
    TF_RND(13) TF_RND(15) TF_RND(26) TF_RND(6)
    x0 += ks2; x1 += ks0 + 5u;
#undef TF_RND
    o0 = x0; o1 = x1;
}

__device__ __forceinline__ float sigf(float x) { return 1.0f / (1.0f + expf(-x)); }

// gumbel from raw bits — identical formula to rounds 1-5
__device__ __forceinline__ float gumbel_from(uint32_t sk0, uint32_t sk1, uint32_t ctr) {
    uint32_t o0, o1;
    threefry2x32(sk0, sk1, 0u, ctr, o0, o1);
    uint32_t bits = o0 ^ o1;
    float f = __uint_as_float((bits >> 9) | 0x3f800000u) - 1.0f;
    const float TINY = 1.17549435e-38f;
    float u = fmaxf(TINY, f * (1.0f - TINY) + TINY);
    return -logf(-logf(u));
}

// ---------------- prep: reorder weights ----------------
__global__ void prep_kernel(const float* __restrict__ Whh, const float* __restrict__ Wih,
                            const float* __restrict__ Wa,  const float* __restrict__ bih,
                            const float* __restrict__ bhh, const float* __restrict__ Wv)
{
    int idx = blockIdx.x * blockDim.x + threadIdx.x;
    if (idx < 2*256*512) {
        // idx = ((p*256 + k)*128 + nl)*4 + g
        int g = idx & 3, nl = (idx >> 2) & 127, k = (idx >> 9) & 255, p = idx >> 17;
        g_WhhR2[idx] = Whh[(size_t)(g*256 + p*128 + nl) * 256 + k];
    }
    if (idx < 64*256*4) {
        int ch = idx >> 10, hh = (idx >> 2) & 255, g = idx & 3;
        ((float*)g_WihR4)[idx] = Wih[(size_t)(g*256 + hh) * 64 + ch];
    }
    if (idx < 128*256) {
        int k = idx >> 8, hh = idx & 255;
        g_WaR[idx] = Wa[(size_t)hh * 128 + k];
    }
    if (idx < 256*64) {
        int k = idx >> 6, v = idx & 63;
        g_WvT[idx] = Wv[(size_t)v * NH + k];
    }
    if (idx < 1024) {
        int hh = idx >> 2, g = idx & 3;
        int gn = g*256 + hh;
        ((float*)g_biasR4)[idx] = bih[gn] + bhh[gn];
    }
    if (idx >= 2*256*512 && idx < 2*256*512 + 2048)
        g_WhhR2[idx] = 0.0f;   // prefetch-overrun pad
}

// ---------------- LSTM epilogue for one pass (bit-identical to R3-R5) ----------------
template<bool hasX>
__device__ __forceinline__ void lstm_epilogue(float* sm, float* hnew, float* cc,
                                              ull (&acc)[7][4], int p, int nl, int b0)
{
    const int hh = p * 128 + nl;
    float4 bb = g_biasR4[hh];
    const int* s_ch = (const int*)sm + OFF_CH;
#pragma unroll
    for (int i = 0; i < 7; i++) {
        float a0[4], a1[4];
#pragma unroll
        for (int g = 0; g < 4; g++) unpack2(acc[i][g], a0[g], a1[g]);
        float hn[2];
#pragma unroll
        for (int ro = 0; ro < 2; ro++) {
            float* ar = ro ? a1 : a0;
            int b = b0 + 2 * i + ro;
            float xx = 0.f, xy = 0.f, xz = 0.f, xw = 0.f;
            if (hasX) {
                int ch = s_ch[b];
                float4 xg = g_WihR4[ch * 256 + hh];
                xx = xg.x; xy = xg.y; xz = xg.z; xw = xg.w;
            }
            float gi = ar[0] + bb.x + xx;
            float gf = ar[1] + bb.y + xy;
            float gg = ar[2] + bb.z + xz;
            float go = ar[3] + bb.w + xw;
            float cv = cc[p * 14 + 2 * i + ro];
            float cn = sigf(gf) * cv + sigf(gi) * tanhf(gg);
            cc[p * 14 + 2 * i + ro] = cn;
            hn[ro] = sigf(go) * tanhf(cn);
        }
        *(ull*)(hnew + hh * HP + b0 + 2 * i) = pack2(hn[0], hn[1]);
    }
}

// ---------------- one LSTM step: LDG-direct W GEMM, no internal bars ----------------
template<bool hasX>
__device__ __forceinline__ void lstm_step(float* sm, const float* hcur, float* hnew,
                                          float* cc, int tid, int nl, int b0)
{
#pragma unroll
    for (int p = 0; p < 2; p++) {
        const float4* Wp = (const float4*)g_WhhR2 + (size_t)p * 32768 + nl;
        ull acc[7][4];
#pragma unroll
        for (int i = 0; i < 7; i++)
#pragma unroll
            for (int g = 0; g < 4; g++) acc[i][g] = 0ull;

        // register prefetch ring, distance 4
        float4 wb[4];
#pragma unroll
        for (int j = 0; j < 4; j++) wb[j] = Wp[(size_t)j * 128];

        const float* hk = hcur + b0;
#pragma unroll 1
        for (int kt = 0; kt < 256; kt += 4) {
#pragma unroll
            for (int j = 0; j < 4; j++) {
                int kk = kt + j;
                float4 w = wb[j];
                wb[j] = Wp[(size_t)(kk + 4) * 128];   // pad covers kk+4 > 255
                ull W0 = pack2(w.x, w.x), W1 = pack2(w.y, w.y);
                ull W2 = pack2(w.z, w.z), W3 = pack2(w.w, w.w);
                const float* hx = hk + kk * HP;
#pragma unroll
                for (int i = 0; i < 7; i++) {
                    ull h2 = *(const ull*)(hx + 2 * i);
                    ffma2(acc[i][0], h2, W0);
                    ffma2(acc[i][1], h2, W1);
                    ffma2(acc[i][2], h2, W2);
                    ffma2(acc[i][3], h2, W3);
                }
            }
        }
        lstm_epilogue<hasX>(sm, hnew, cc, acc, p, nl, b0);
    }
    __syncthreads();
}

// ---------------- per-row reduction + gumbel sample (bit-identical to R4/R5) ----------------
__device__ __forceinline__ void reduce_row(float* sm, int r, int base, int lane,
        float* __restrict__ out, int t, uint32_t sk0, uint32_t sk1)
{
    int* si = (int*)sm;
    int gb = base + r;
    float la0 = sm[OFF_LG + r * 64 + 2 * lane];
    float la1 = sm[OFF_LG + r * 64 + 2 * lane + 1];
    float m = fmaxf(la0, la1);
#pragma unroll
    for (int o = 16; o; o >>= 1) m = fmaxf(m, __shfl_xor_sync(0xffffffffu, m, o));
    float S = expf(la0 - m) + expf(la1 - m);
#pragma unroll
    for (int o = 16; o; o >>= 1) S += __shfl_xor_sync(0xffffffffu, S, o);
    float lse = logf(S);
    float lp0 = (la0 - m) - lse;
    float lp1 = (la1 - m) - lse;
    float pt = expf(lp0) * lp0 + expf(lp1) * lp1;
#pragma unroll
    for (int o = 16; o; o >>= 1) pt += __shfl_xor_sync(0xffffffffu, pt, o);
    float g0 = gumbel_from(sk0, sk1, (uint32_t)(gb * NV + 2 * lane));
    float g1 = gumbel_from(sk0, sk1, (uint32_t)(gb * NV + 2 * lane + 1));
    float z0 = la0 + g0, z1 = la1 + g1;
    float z; int idx;
    if (z1 > z0) { z = z1; idx = 2 * lane + 1; }
    else         { z = z0; idx = 2 * lane; }
#pragma unroll
    for (int o = 16; o; o >>= 1) {
        float oz = __shfl_xor_sync(0xffffffffu, z, o);
        int   oi = __shfl_xor_sync(0xffffffffu, idx, o);
        if (oz > z || (oz == z && oi < idx)) { z = oz; idx = oi; }
    }
    float lpA = __shfl_sync(0xffffffffu, lp0, idx >> 1);
    float lpB = __shfl_sync(0xffffffffu, lp1, idx >> 1);
    float lp = (idx & 1) ? lpB : lpA;
    if (lane == 0) {
        si[OFF_CH + r] = idx;
        sm[OFF_SLP + r] += lp;
        sm[OFF_PLP + r] += pt;
        sm[OFF_EP + r] *= expf(lp);
        if (gb < NB) out[(size_t)gb * NL + t] = (float)idx;
    }
}

// ---------------- sampling: logits (bit-exact) + row-parallel reductions ----------------
__device__ __forceinline__ void sample_step(float* sm, const float* hcur,
        const float* __restrict__ bv, float* __restrict__ out, int t, int base,
        int tid, uint32_t sk0, uint32_t sk1)
{
    const int sbg = tid >> 6;          // 8 groups of 7 rows
    const int v = tid & 63;
    const int b0s = sbg * 7;
    const int p0 = (sbg & 1) ? 1 : 0;  // aligned pair base
    const int sc = (sbg & 1) ? 0 : 6;  // leftover scalar row
    float bvv = bv[v];
    ull accp[3];
    accp[0] = pack2(bvv, bvv); accp[1] = accp[0]; accp[2] = accp[0];
    float accs = bvv;
    const float* hs = hcur + b0s;
    const float* wvk = g_WvT + v;
#pragma unroll 4
    for (int kk = 0; kk < NH; kk++) {
        float w = wvk[kk * 64];
        ull w2 = pack2(w, w);
        ffma2(accp[0], *(const ull*)(hs + kk * HP + p0), w2);
        ffma2(accp[1], *(const ull*)(hs + kk * HP + p0 + 2), w2);
        ffma2(accp[2], *(const ull*)(hs + kk * HP + p0 + 4), w2);
        accs = fmaf(hs[kk * HP + sc], w, accs);
    }
#pragma unroll
    for (int j = 0; j < 3; j++) {
        float lo, hi; unpack2(accp[j], lo, hi);
        sm[OFF_LG + (b0s + p0 + 2*j    ) * 64 + v] = lo;
        sm[OFF_LG + (b0s + p0 + 2*j + 1) * 64 + v] = hi;
    }
    sm[OFF_LG + (b0s + sc) * 64 + v] = accs;
    __syncthreads();

    const int warp = tid >> 5, lane = tid & 31;
    for (int r = warp; r < NBR; r += 16)
        reduce_row(sm, r, base, lane, out, t, sk0, sk1);
    __syncthreads();
}

// ---------------- fused persistent rollout kernel ----------------
__global__ __launch_bounds__(NT, 1) void sender_kernel(
    const float* __restrict__ attr, const float* __restrict__ bv,
    const float* __restrict__ ba, float* __restrict__ out, Keys keys)
{
    extern __shared__ float sm[];
    const int tid = threadIdx.x;
    const int bq = tid >> 7;        // 4 groups
    const int nl = tid & 127;       // 128 n-columns
    const int b0 = bq * 14;         // 14 rows (7 f32x2 pairs)
    const int base = blockIdx.x * NBR;

    float cc[28];
#pragma unroll
    for (int i = 0; i < 28; i++) cc[i] = 0.0f;

    if (tid < NBR) { sm[OFF_SLP + tid] = 0.0f; sm[OFF_PLP + tid] = 0.0f; sm[OFF_EP + tid] = 1.0f; }

    // stage attr tile [k 128][b] stride HP into hB region
    for (int idx = tid; idx < NBR * 32; idx += NT) {
        int b = idx >> 5, f4 = idx & 31;
        int gb = base + b;
        float4 a = make_float4(0.f, 0.f, 0.f, 0.f);
        if (gb < NB) a = ((const float4*)attr)[(size_t)gb * 32 + f4];
        sm[OFF_HB + (f4*4+0)*HP + b] = a.x;
        sm[OFF_HB + (f4*4+1)*HP + b] = a.y;
        sm[OFF_HB + (f4*4+2)*HP + b] = a.z;
        sm[OFF_HB + (f4*4+3)*HP + b] = a.w;
    }
    __syncthreads();

    // h0 = attr @ W_a^T + b_a  (identical arithmetic to R2-R5)
#pragma unroll
    for (int p = 0; p < 2; p++) {
        const int hh = p * 128 + nl;
        ull acc[7];
#pragma unroll
        for (int i = 0; i < 7; i++) acc[i] = 0ull;
        const float* wr = g_WaR + hh;
        const float* ak = sm + OFF_HB + b0;
#pragma unroll 4
        for (int k = 0; k < NA; k++) {
            float w = wr[k * 256];
            ull w2 = pack2(w, w);
#pragma unroll
            for (int i = 0; i < 7; i++) {
                ull h2 = *(const ull*)(ak + k * HP + 2 * i);
                ffma2(acc[i], h2, w2);
            }
        }
        float bbv = ba[hh];
#pragma unroll
        for (int i = 0; i < 7; i++) {
            float lo, hi; unpack2(acc[i], lo, hi);
            *(ull*)(sm + OFF_HA + hh * HP + b0 + 2 * i) = pack2(lo + bbv, hi + bbv);
        }
    }
    __syncthreads();

    float* hA = sm + OFF_HA;
    float* hB = sm + OFF_HB;

    // start-token step (x = 0): hA -> hB
    lstm_step<false>(sm, hA, hB, cc, tid, nl, b0);

    float* hc = hB;
    float* hn = hA;
    for (int t = 0; t < NL; t++) {
        sample_step(sm, hc, bv, out, t, base, tid, keys.a[t], keys.b[t]);
        if (t < NL - 1) {
            lstm_step<true>(sm, hc, hn, cc, tid, nl, b0);
            float* tmp = hc; hc = hn; hn = tmp;
        }
    }

    for (int i = tid; i < NBR; i += NT) {
        int gb = base + i;
        if (gb < NB) {
            out[NB*NL + gb]        = sm[OFF_SLP + i];
            out[NB*NL + NB + gb]   = sm[OFF_PLP + i];
            out[NB*NL + 2*NB + gb] = sm[OFF_EP + i];
        }
    }
}

// ---------------- launcher ----------------
extern "C" void kernel_launch(void* const* d_in, const int* in_sizes, int n_in,
                              void* d_out, int out_size)
{
    const float* attr = (const float*)d_in[0];
    const float* W_a  = (const float*)d_in[1];
    const float* b_a  = (const float*)d_in[2];
    const float* W_ih = (const float*)d_in[3];
    const float* W_hh = (const float*)d_in[4];
    const float* b_ih = (const float*)d_in[5];
    const float* b_hh = (const float*)d_in[6];
    const float* W_v  = (const float*)d_in[7];
    const float* b_v  = (const float*)d_in[8];
    float* out = (float*)d_out;

    Keys keys;
    for (int t = 0; t < NL; t++) {
        uint32_t s0, s1;
        threefry2x32(0u, 42u, 0u, (uint32_t)t, s0, s1);
        keys.a[t] = s0; keys.b[t] = s1;
    }

    static int smem_set = 0;
    if (!smem_set) {
        cudaFuncSetAttribute(sender_kernel, cudaFuncAttributeMaxDynamicSharedMemorySize,
                             SMEM_FLOATS * sizeof(float));
        smem_set = 1;
    }

    prep_kernel<<<1032, 256>>>(W_hh, W_ih, W_a, b_ih, b_hh, W_v);
    sender_kernel<<<NBLK, NT, SMEM_FLOATS * sizeof(float)>>>(attr, b_v, b_a, out, keys);
}